// round 5
// baseline (speedup 1.0000x reference)
#include <cuda_runtime.h>
#include <cuda_bf16.h>

// Cox partial-likelihood loss.
//   survtime = y_true[:,0]; censor = (y_true[:,1] != 0)
//   theta    = hazard_pred.flatten()
//   risk_sum[i] = sum_j exp(theta[j]) * (survtime[j] >= survtime[i])
//   loss = -mean((theta - log(risk_sum)) * censor)
//
// O(N^2) masked reduction tiled through shared memory; the N x N risk matrix
// is never materialized. Deterministic (fixed-slot partials, fixed-order
// reductions, no atomics). Graph-capturable: 3 plain launches, no allocs.
//
// Inner loop: per j, one LDS.64 broadcast amortized over 4 i's; per (i,j)
// pair FSET.BF.GE + FFMA = 2 fixed-lat instrs on alternating alu/fma pipes.

#define MAX_N       8192
#define J_TILES     32
#define J_CHUNK_MAX ((MAX_N + J_TILES - 1) / J_TILES)   // 256
#define THREADS     256
#define I_PER_THR   4
#define I_TILE      (THREADS * I_PER_THR)               // 1024
#define RED_THREADS 512
#define MAX_BLOCKS_RED 64

// Scratch (allocation-free): partial risk sums per (j-tile, i), block sums.
__device__ float g_partial[J_TILES * MAX_N];
__device__ float g_bsum[MAX_BLOCKS_RED];

// ---------------------------------------------------------------------------
// Kernel 1: partial risk sums.
// blockIdx.x = i-tile (I_TILE i's), blockIdx.y = j-tile (jchunk j's).
// ---------------------------------------------------------------------------
__global__ void __launch_bounds__(THREADS)
risk_kernel(const float* __restrict__ y_true,
            const float* __restrict__ theta,
            int N, int jchunk)
{
    __shared__ float2 sj[J_CHUNK_MAX];

    const int itile = blockIdx.x;
    const int jt    = blockIdx.y;
    const int j0    = jt * jchunk;
    int jn = N - j0;
    if (jn > jchunk) jn = jchunk;
    if (jn < 0) jn = 0;

    // Cooperative stage: (time, exp(theta)) for this j-chunk.
    for (int j = threadIdx.x; j < jn; j += THREADS) {
        float t = y_true[2 * (j0 + j)];
        float e = __expf(theta[j0 + j]);
        sj[j] = make_float2(t, e);
    }
    __syncthreads();

    const int ibase = itile * I_TILE + threadIdx.x;
    float ti[I_PER_THR];
    #pragma unroll
    for (int k = 0; k < I_PER_THR; ++k) {
        int i = ibase + k * THREADS;
        ti[k] = (i < N) ? y_true[2 * i] : 0.0f;
    }

    float acc[I_PER_THR];
    #pragma unroll
    for (int k = 0; k < I_PER_THR; ++k) acc[k] = 0.0f;

    #pragma unroll 8
    for (int j = 0; j < jn; ++j) {
        float2 v = sj[j];                       // LDS.64 broadcast
        #pragma unroll
        for (int k = 0; k < I_PER_THR; ++k) {
            float m = (v.x >= ti[k]) ? 1.0f : 0.0f;   // FSET.BF.GE
            acc[k] = fmaf(v.y, m, acc[k]);            // FFMA
        }
    }

    #pragma unroll
    for (int k = 0; k < I_PER_THR; ++k) {
        int i = ibase + k * THREADS;
        if (i < N) g_partial[jt * N + i] = acc[k];
    }
}

// ---------------------------------------------------------------------------
// Kernel 2: per-i contribution + block reduction.
// contribution_i = (theta_i - log(risk_sum_i)) * censor_i
// ---------------------------------------------------------------------------
__global__ void __launch_bounds__(RED_THREADS)
contrib_kernel(const float* __restrict__ y_true,
               const float* __restrict__ theta,
               int N)
{
    __shared__ float red[RED_THREADS];

    const int i = blockIdx.x * RED_THREADS + threadIdx.x;
    float c = 0.0f;
    if (i < N) {
        float risk = 0.0f;
        #pragma unroll
        for (int jt = 0; jt < J_TILES; ++jt)
            risk += g_partial[jt * N + i];
        float censor = (y_true[2 * i + 1] != 0.0f) ? 1.0f : 0.0f;
        c = (theta[i] - __logf(risk)) * censor;
    }

    red[threadIdx.x] = c;
    __syncthreads();
    #pragma unroll
    for (int s = RED_THREADS / 2; s >= 32; s >>= 1) {
        if (threadIdx.x < s) red[threadIdx.x] += red[threadIdx.x + s];
        __syncthreads();
    }
    if (threadIdx.x < 32) {
        float v = red[threadIdx.x];
        #pragma unroll
        for (int o = 16; o > 0; o >>= 1)
            v += __shfl_down_sync(0xFFFFFFFFu, v, o);
        if (threadIdx.x == 0) g_bsum[blockIdx.x] = v;
    }
}

// ---------------------------------------------------------------------------
// Kernel 3: final scalar. One warp, deterministic order.
// ---------------------------------------------------------------------------
__global__ void final_kernel(float* __restrict__ out, int nblocks, int N)
{
    float s = 0.0f;
    for (int b = threadIdx.x; b < nblocks; b += 32)
        s += g_bsum[b];
    #pragma unroll
    for (int o = 16; o > 0; o >>= 1)
        s += __shfl_down_sync(0xFFFFFFFFu, s, o);
    if (threadIdx.x == 0)
        out[0] = -s / (float)N;
}

// ---------------------------------------------------------------------------
extern "C" void kernel_launch(void* const* d_in, const int* in_sizes, int n_in,
                              void* d_out, int out_size)
{
    // Identify inputs by size: y_true has 2N elements, hazard_pred has N.
    const float* y_true;
    const float* theta;
    int N;
    if (in_sizes[0] == 2 * in_sizes[1]) {
        y_true = (const float*)d_in[0];
        theta  = (const float*)d_in[1];
        N = in_sizes[1];
    } else {
        theta  = (const float*)d_in[0];
        y_true = (const float*)d_in[1];
        N = in_sizes[0];
    }

    float* out = (float*)d_out;

    const int jchunk  = (N + J_TILES - 1) / J_TILES;    // <= J_CHUNK_MAX
    const int itiles  = (N + I_TILE - 1) / I_TILE;
    const int rblocks = (N + RED_THREADS - 1) / RED_THREADS;

    dim3 grid1(itiles, J_TILES);
    risk_kernel<<<grid1, THREADS>>>(y_true, theta, N, jchunk);
    contrib_kernel<<<rblocks, RED_THREADS>>>(y_true, theta, N);
    final_kernel<<<1, 32>>>(out, rblocks, N);
}